// round 16
// baseline (speedup 1.0000x reference)
#include <cuda_runtime.h>
#include <cuda_fp16.h>
#include <math.h>
#include <stdint.h>

// Problem constants
#define TOTAL  32768
#define D      1280
#define NSEG   128
#define DHEAD  512

// GEMM tiling
#define TILE_M   128
#define TILE_N   128
#define KCH      64                 // K elements per chunk (128B fp16 row)
#define NT_TILES (D / TILE_N)       // 10
#define MT_TILES (TOTAL / TILE_M)   // 256
#define KCHUNKS  (D / KCH)          // 20
#define ATILE_B  (TILE_M * 128)     // 16384
#define BTILE_B  (TILE_N * 128)     // 16384
#define STAGE_B  (ATILE_B + BTILE_B)   // 32768
#define NSTAGES  3
#define DSMEM    (NSTAGES * STAGE_B + 1024)   // ~97KB -> 2 CTAs/SM

// prep kernel block ranges
#define NB_CONVF (TOTAL * (D / 16) / 512)          // 5120
#define NB_CONVW ((D * (D / 8) + 511) / 512)       // 400
#define NB_MISC  ((DHEAD * D + 511) / 512)         // 1280
#define NB_PREP  (NB_CONVF + NB_CONVW + NB_MISC)   // 6800

#define PSPLIT   8                  // segment split factor for pooling
#define SEGB     4                  // segments per head block

// ---------------- scratch (static device globals; no allocation) -----------
__device__ float g_s[TOTAL];
__device__ float g_spart[NT_TILES * TOTAL];
__device__ float g_att[TOTAL];
__device__ int   g_start[NSEG + 1];
__device__ float g_poolp[PSPLIT * NSEG * D];   // split pooling partials
__device__ float g_W1t[D * DHEAD];
// fp16 operands, tile-contiguous + SW128 pre-swizzled
__device__ __align__(1024) unsigned char g_Fh[(size_t)TOTAL * D * 2];
__device__ __align__(1024) unsigned char g_Wh[(size_t)D * D * 2];

// ---------------------------- PTX helpers ----------------------------------
__device__ __forceinline__ uint32_t smem_u32(const void* p) {
    uint32_t a;
    asm("{ .reg .u64 t; cvta.to.shared.u64 t, %1; cvt.u32.u64 %0, t; }"
        : "=r"(a) : "l"(p));
    return a;
}
__device__ __forceinline__ uint32_t swz128(uint32_t b) {
    return b ^ ((b >> 3) & 0x70);
}

#define MBARRIER_INIT(addr, cnt) \
    asm volatile("mbarrier.init.shared.b64 [%0], %1;" :: "r"(addr), "r"(cnt) : "memory")
#define MBARRIER_EXPECT_TX(addr, bytes) \
    asm volatile("mbarrier.arrive.expect_tx.shared.b64 _, [%0], %1;" :: "r"(addr), "r"(bytes) : "memory")
#define MBARRIER_ARRIVE(addr) \
    asm volatile("mbarrier.arrive.release.cta.shared.b64 _, [%0];" :: "r"(addr) : "memory")
#define MBARRIER_WAIT_PARITY(addr, par) do {                                   \
    uint32_t _m = (addr); uint32_t _p = (par); uint32_t _d;                    \
    asm volatile("{\n\t.reg .pred p;\n\t"                                      \
        "mbarrier.try_wait.parity.acquire.cta.shared::cta.b64 p, [%1], %2;\n\t"\
        "selp.b32 %0, 1, 0, p;\n\t}" : "=r"(_d) : "r"(_m), "r"(_p) : "memory");\
    if (!_d) {                                                                 \
        asm volatile("{\n\t.reg .pred P1;\n\t"                                 \
        "WL_%=:\n\t"                                                           \
        "mbarrier.try_wait.parity.acquire.cta.shared::cta.b64 P1, [%0], %1, 0x989680;\n\t"\
        "@P1 bra.uni WD_%=;\n\t"                                               \
        "bra.uni WL_%=;\n\t"                                                   \
        "WD_%=:\n\t}" :: "r"(_m), "r"(_p) : "memory");                         \
    }                                                                          \
} while (0)

__device__ __forceinline__ void bulk_cp(uint32_t dst, const void* src,
                                        uint32_t bytes, uint32_t mbar) {
    asm volatile(
        "cp.async.bulk.shared::cluster.global.mbarrier::complete_tx::bytes [%0], [%1], %2, [%3];"
        :: "r"(dst), "l"(src), "r"(bytes), "r"(mbar) : "memory");
}

#define LDSM4(r, addr) \
    asm volatile("ldmatrix.sync.aligned.m8n8.x4.shared.b16 {%0,%1,%2,%3}, [%4];" \
        : "=r"((r)[0]), "=r"((r)[1]), "=r"((r)[2]), "=r"((r)[3]) : "r"(addr))

#define MMA16816(c, a, b0, b1) \
    asm volatile("mma.sync.aligned.m16n8k16.row.col.f32.f16.f16.f32 " \
        "{%0,%1,%2,%3}, {%4,%5,%6,%7}, {%8,%9}, {%0,%1,%2,%3};" \
        : "+f"((c)[0]), "+f"((c)[1]), "+f"((c)[2]), "+f"((c)[3]) \
        : "r"((a)[0]), "r"((a)[1]), "r"((a)[2]), "r"((a)[3]), "r"(b0), "r"(b1))

// ---------------------------------------------------------------------------
// fp32 -> fp16 pack helper
// ---------------------------------------------------------------------------
__device__ __forceinline__ uint4 pack8h(float4 x0, float4 x1) {
    uint32_t h[4];
    __half2 p0 = __floats2half2_rn(x0.x, x0.y); h[0] = *(uint32_t*)&p0;
    __half2 p1 = __floats2half2_rn(x0.z, x0.w); h[1] = *(uint32_t*)&p1;
    __half2 p2 = __floats2half2_rn(x1.x, x1.y); h[2] = *(uint32_t*)&p2;
    __half2 p3 = __floats2half2_rn(x1.z, x1.w); h[3] = *(uint32_t*)&p3;
    return make_uint4(h[0], h[1], h[2], h[3]);
}

// ---------------------------------------------------------------------------
// K0: merged prep kernel — convF + convW + misc in one launch (R14 exact).
// ---------------------------------------------------------------------------
__global__ void __launch_bounds__(512)
prep_kernel(const float* __restrict__ F, const float* __restrict__ W,
            const float* __restrict__ W1, const int* __restrict__ ids) {
    const int bid = blockIdx.x;
    if (bid < NB_CONVF) {
        int idx = bid * 512 + threadIdx.x;
        int row = idx / (D / 16), cg2 = idx - row * (D / 16);
        int mt = row >> 7, r = row & 127;
        int kc = cg2 >> 2, gi0 = (cg2 & 3) * 2;
        const float4* src = (const float4*)(F + (size_t)row * D + kc * 64 + gi0 * 8);
        uint4 h0 = pack8h(src[0], src[1]);
        uint4 h1 = pack8h(src[2], src[3]);
        size_t base = (size_t)(mt * KCHUNKS + kc) * ATILE_B;
        uint32_t rb = (uint32_t)(r * 128 + gi0 * 16);
        *(uint4*)(g_Fh + base + swz128(rb)) = h0;
        *(uint4*)(g_Fh + base + swz128(rb + 16)) = h1;
    } else if (bid < NB_CONVF + NB_CONVW) {
        int idx = (bid - NB_CONVF) * 512 + threadIdx.x;
        if (idx < D * (D / 8)) {
            int row = idx / (D / 8), cg = idx - row * (D / 8);
            int nt = row >> 7, r = row & 127;
            int kc = cg >> 3, gi = cg & 7;
            const float4* src = (const float4*)(W + (size_t)row * D + cg * 8);
            uint4 hi = pack8h(src[0], src[1]);
            size_t base = (size_t)(nt * KCHUNKS + kc) * BTILE_B;
            uint32_t off = swz128((uint32_t)(r * 128 + gi * 16));
            *(uint4*)(g_Wh + base + off) = hi;
        }
    } else {
        int idx = (bid - NB_CONVF - NB_CONVW) * 512 + threadIdx.x;
        if (idx < DHEAD * D) {
            int n = idx / D, k = idx - n * D;
            g_W1t[k * DHEAD + n] = W1[idx];
        }
        if (idx < TOTAL) {
            if (idx == 0) { g_start[ids[0]] = 0; g_start[NSEG] = TOTAL; }
            else if (ids[idx] != ids[idx - 1]) g_start[ids[idx]] = idx;
        }
    }
}

// ---------------------------------------------------------------------------
// K1: single-pass fp16 GEMM + tanh/dot-v epilogue, occupancy 2 (R10 exact).
// ---------------------------------------------------------------------------
__global__ void __launch_bounds__(256, 2)
gemm_tc_kernel(const float* __restrict__ bw, const float* __restrict__ v) {
    extern __shared__ __align__(16) char smem_raw[];
    __shared__ __align__(8) unsigned long long full_mb[NSTAGES];
    __shared__ __align__(8) unsigned long long empty_mb[NSTAGES];
    __shared__ float red[2][TILE_M];

    const uint32_t TILES = (smem_u32(smem_raw) + 1023) & ~1023u;
    const uint32_t FB = smem_u32(&full_mb[0]);
    const uint32_t EB = smem_u32(&empty_mb[0]);

    const int tid = threadIdx.x, wid = tid >> 5, lane = tid & 31;
    const int mt = blockIdx.x / NT_TILES, nt = blockIdx.x % NT_TILES;
    const int wm = wid >> 1, wn = wid & 1;   // 4 m-warps x 2 n-warps

    if (tid == 0) {
#pragma unroll
        for (int s = 0; s < NSTAGES; ++s) {
            MBARRIER_INIT(FB + s * 8, 1);
            MBARRIER_INIT(EB + s * 8, 256);
        }
    }
    __syncthreads();

    const unsigned char* aHi = g_Fh + (size_t)mt * KCHUNKS * ATILE_B;
    const unsigned char* bHi = g_Wh + (size_t)nt * KCHUNKS * BTILE_B;

    if (tid == 0) {
#pragma unroll
        for (int k = 0; k < NSTAGES - 1; ++k) {
            uint32_t st = TILES + k * STAGE_B;
            MBARRIER_EXPECT_TX(FB + k * 8, (uint32_t)STAGE_B);
            bulk_cp(st,           aHi + (size_t)k * ATILE_B, ATILE_B, FB + k * 8);
            bulk_cp(st + ATILE_B, bHi + (size_t)k * BTILE_B, BTILE_B, FB + k * 8);
        }
    }

    // ldmatrix address components (within tile, swizzled)
    const uint32_t xm = (lane & 7) << 4;
    const uint32_t a_rb = (uint32_t)(wm * 32 + (lane & 15)) * 128;
    const uint32_t a_cb = (uint32_t)((lane >> 4) * 16);
    const uint32_t b_rb = (uint32_t)(wn * 64 + (lane & 7) + ((lane >> 4) & 1) * 8) * 128;
    const uint32_t b_cb = (uint32_t)(((lane >> 3) & 1) * 16);

    float acc[2][8][4];
#pragma unroll
    for (int t = 0; t < 2; ++t)
#pragma unroll
        for (int j = 0; j < 8; ++j)
#pragma unroll
            for (int e = 0; e < 4; ++e) acc[t][j][e] = 0.f;

    for (int k = 0; k < KCHUNKS; ++k) {
        const int s = k % NSTAGES;
        MBARRIER_WAIT_PARITY(FB + s * 8, (uint32_t)((k / NSTAGES) & 1));

        if (tid == 0 && k + NSTAGES - 1 < KCHUNKS) {
            const int kn = k + NSTAGES - 1;
            const int s2 = kn % NSTAGES;
            if (kn >= NSTAGES)
                MBARRIER_WAIT_PARITY(EB + s2 * 8, (uint32_t)((kn / NSTAGES - 1) & 1));
            uint32_t st2 = TILES + s2 * STAGE_B;
            MBARRIER_EXPECT_TX(FB + s2 * 8, (uint32_t)STAGE_B);
            bulk_cp(st2,           aHi + (size_t)kn * ATILE_B, ATILE_B, FB + s2 * 8);
            bulk_cp(st2 + ATILE_B, bHi + (size_t)kn * BTILE_B, BTILE_B, FB + s2 * 8);
        }

        const uint32_t st = TILES + s * STAGE_B;
        const uint32_t stB = st + ATILE_B;
#pragma unroll
        for (int q = 0; q < 4; ++q) {
            uint32_t Ah[2][4], Bh[4][4];
            const uint32_t qa = (q * 32 + a_cb) ^ xm;
            const uint32_t qb = (q * 32 + b_cb) ^ xm;
#pragma unroll
            for (int t = 0; t < 2; ++t)
                LDSM4(Ah[t], st + a_rb + t * 2048 + qa);
#pragma unroll
            for (int g = 0; g < 4; ++g)
                LDSM4(Bh[g], stB + b_rb + g * 2048 + qb);
#pragma unroll
            for (int t = 0; t < 2; ++t)
#pragma unroll
                for (int g = 0; g < 4; ++g)
#pragma unroll
                    for (int h = 0; h < 2; ++h)
                        MMA16816(acc[t][g * 2 + h], Ah[t], Bh[g][h * 2], Bh[g][h * 2 + 1]);
        }
        MBARRIER_ARRIVE(EB + s * 8);
    }

    // epilogue: srow[r] = sum_n tanh(acc + bw[n]) * v[n]
#pragma unroll
    for (int t = 0; t < 2; ++t) {
        float s0 = 0.f, s1 = 0.f;
#pragma unroll
        for (int j = 0; j < 8; ++j) {
            int n0 = nt * TILE_N + wn * 64 + j * 8 + (lane & 3) * 2;
            float bw0 = __ldg(&bw[n0]),     v0 = __ldg(&v[n0]);
            float bw1 = __ldg(&bw[n0 + 1]), v1 = __ldg(&v[n0 + 1]);
            s0 += tanhf(acc[t][j][0] + bw0) * v0 + tanhf(acc[t][j][1] + bw1) * v1;
            s1 += tanhf(acc[t][j][2] + bw0) * v0 + tanhf(acc[t][j][3] + bw1) * v1;
        }
        s0 += __shfl_xor_sync(0xFFFFFFFFu, s0, 1);
        s0 += __shfl_xor_sync(0xFFFFFFFFu, s0, 2);
        s1 += __shfl_xor_sync(0xFFFFFFFFu, s1, 1);
        s1 += __shfl_xor_sync(0xFFFFFFFFu, s1, 2);
        if ((lane & 3) == 0) {
            int r = wm * 32 + t * 16 + (lane >> 2);
            red[wn][r] = s0;
            red[wn][r + 8] = s1;
        }
    }
    __syncthreads();
    if (tid < TILE_M)
        g_spart[nt * TOTAL + mt * TILE_M + tid] = red[0][tid] + red[1][tid];
}

// ---------------------------------------------------------------------------
// K2: per-segment stable softmax (folds the 10-way partial reduction inline)
// ---------------------------------------------------------------------------
__global__ void softmax_kernel() {
    __shared__ float sm[256];
    const int b = blockIdx.x, tid = threadIdx.x;
    const int s0 = g_start[b], s1 = g_start[b + 1];
    float m = -1e30f;
    for (int i = s0 + tid; i < s1; i += 256) {
        float t = 0.f;
#pragma unroll
        for (int nt = 0; nt < NT_TILES; ++nt) t += g_spart[nt * TOTAL + i];
        g_s[i] = t;
        m = fmaxf(m, t);
    }
    sm[tid] = m; __syncthreads();
    for (int st = 128; st >= 1; st >>= 1) {
        if (tid < st) sm[tid] = fmaxf(sm[tid], sm[tid + st]);
        __syncthreads();
    }
    m = sm[0]; __syncthreads();
    float z = 0.f;
    for (int i = s0 + tid; i < s1; i += 256) z += expf(g_s[i] - m);
    sm[tid] = z; __syncthreads();
    for (int st = 128; st >= 1; st >>= 1) {
        if (tid < st) sm[tid] += sm[tid + st];
        __syncthreads();
    }
    float inv = 1.f / sm[0];
    for (int i = s0 + tid; i < s1; i += 256)
        g_att[i] = expf(g_s[i] - m) * inv;
}

// ---------------------------------------------------------------------------
// K3: attention-weighted pooling, segment split 8-way for parallelism.
// grid (D/128, NSEG, PSPLIT); split z handles a deterministic eighth.
// ---------------------------------------------------------------------------
__global__ void pool_kernel(const float* __restrict__ F) {
    const int seg = blockIdx.y;
    const int z = blockIdx.z;
    const int col = blockIdx.x * 128 + threadIdx.x;
    const int s0 = g_start[seg], s1 = g_start[seg + 1];
    const int len = s1 - s0;
    const int i0 = s0 + (len * z) / PSPLIT;
    const int i1 = s0 + (len * (z + 1)) / PSPLIT;
    float acc = 0.f;
    int i = i0;
    for (; i + 3 < i1; i += 4) {
        float a0 = g_att[i], a1 = g_att[i + 1], a2 = g_att[i + 2], a3 = g_att[i + 3];
        float f0 = F[(size_t)(i + 0) * D + col];
        float f1 = F[(size_t)(i + 1) * D + col];
        float f2 = F[(size_t)(i + 2) * D + col];
        float f3 = F[(size_t)(i + 3) * D + col];
        acc = fmaf(a0, f0, acc); acc = fmaf(a1, f1, acc);
        acc = fmaf(a2, f2, acc); acc = fmaf(a3, f3, acc);
    }
    for (; i < i1; ++i) acc = fmaf(g_att[i], F[(size_t)i * D + col], acc);
    g_poolp[((size_t)z * NSEG + seg) * D + col] = acc;
}

// ---------------------------------------------------------------------------
// K4: seg-grouped MLP head — 32 blocks x 4 segments; W1t read once per block.
// ---------------------------------------------------------------------------
__global__ void __launch_bounds__(DHEAD)
head_kernel(const float* __restrict__ b1, const float* __restrict__ W2,
            const float* __restrict__ b2, float* __restrict__ out) {
    __shared__ __align__(16) float p[SEGB][D];    // 20KB
    __shared__ float red[SEGB][DHEAD];            // 8KB
    const int sb = blockIdx.x;                     // 0..31
    const int t = threadIdx.x;

    // stage pooled vectors (sum PSPLIT partials in fixed order)
#pragma unroll
    for (int s = 0; s < SEGB; ++s) {
        const int seg = sb * SEGB + s;
        for (int k = t; k < D; k += DHEAD) {
            float sum = 0.f;
#pragma unroll
            for (int z = 0; z < PSPLIT; ++z)
                sum += g_poolp[((size_t)z * NSEG + seg) * D + k];
            p[s][k] = sum;
        }
    }
    __syncthreads();

    float acc[SEGB];
#pragma unroll
    for (int s = 0; s < SEGB; ++s) acc[s] = 0.f;

    for (int k = 0; k < D; k += 4) {
        float w0 = g_W1t[(k + 0) * DHEAD + t];
        float w1 = g_W1t[(k + 1) * DHEAD + t];
        float w2 = g_W1t[(k + 2) * DHEAD + t];
        float w3 = g_W1t[(k + 3) * DHEAD + t];
#pragma unroll
        for (int s = 0; s < SEGB; ++s) {
            float4 pv = *(const float4*)&p[s][k];
            acc[s] = fmaf(w0, pv.x, acc[s]);
            acc[s] = fmaf(w1, pv.y, acc[s]);
            acc[s] = fmaf(w2, pv.z, acc[s]);
            acc[s] = fmaf(w3, pv.w, acc[s]);
        }
    }

    const float b1t = b1[t], w2t = W2[t];
#pragma unroll
    for (int s = 0; s < SEGB; ++s)
        red[s][t] = fmaxf(acc[s] + b1t, 0.f) * w2t;
    __syncthreads();
    for (int st = DHEAD / 2; st >= 1; st >>= 1) {
        if (t < st) {
#pragma unroll
            for (int s = 0; s < SEGB; ++s) red[s][t] += red[s][t + st];
        }
        __syncthreads();
    }
    if (t < SEGB) out[sb * SEGB + t] = red[t][0] + b2[0];
}

// ---------------------------------------------------------------------------
extern "C" void kernel_launch(void* const* d_in, const int* in_sizes, int n_in,
                              void* d_out, int out_size) {
    const float* features = (const float*)d_in[0];
    const float* Ww       = (const float*)d_in[1];
    const float* bw       = (const float*)d_in[2];
    const float* v        = (const float*)d_in[3];
    const float* W1       = (const float*)d_in[4];
    const float* b1       = (const float*)d_in[5];
    const float* W2       = (const float*)d_in[6];
    const float* b2       = (const float*)d_in[7];
    const int*   seg_ids  = (const int*)d_in[8];
    float* out = (float*)d_out;

    cudaFuncSetAttribute(gemm_tc_kernel,
                         cudaFuncAttributeMaxDynamicSharedMemorySize, DSMEM);

    prep_kernel<<<NB_PREP, 512>>>(features, Ww, W1, seg_ids);
    gemm_tc_kernel<<<MT_TILES * NT_TILES, 256, DSMEM>>>(bw, v);
    softmax_kernel<<<NSEG, 256>>>();
    pool_kernel<<<dim3(D / 128, NSEG, PSPLIT), 128>>>(features);
    head_kernel<<<NSEG / SEGB, DHEAD>>>(b1, W2, b2, out);
}

// round 17
// speedup vs baseline: 1.1795x; 1.1795x over previous
#include <cuda_runtime.h>
#include <cuda_fp16.h>
#include <math.h>
#include <stdint.h>

// Problem constants
#define TOTAL  32768
#define D      1280
#define NSEG   128
#define DHEAD  512

// GEMM tiling
#define TILE_M   128
#define TILE_N   128
#define KCH      64                 // K elements per chunk (128B fp16 row)
#define NT_TILES (D / TILE_N)       // 10
#define MT_TILES (TOTAL / TILE_M)   // 256
#define KCHUNKS  (D / KCH)          // 20
#define ATILE_B  (TILE_M * 128)     // 16384
#define BTILE_B  (TILE_N * 128)     // 16384
#define STAGE_B  (ATILE_B + BTILE_B)   // 32768
#define NSTAGES  3
#define DSMEM    (NSTAGES * STAGE_B + 1024)   // ~97KB -> 2 CTAs/SM

// prep kernel block ranges
#define NB_CONVF (TOTAL * (D / 16) / 512)          // 5120
#define NB_CONVW ((D * (D / 8) + 511) / 512)       // 400
#define NB_MISC  ((DHEAD * D + 511) / 512)         // 1280
#define NB_PREP  (NB_CONVF + NB_CONVW + NB_MISC)   // 6800

#define PSPLIT   8                  // segment split factor for pooling

// ---------------- scratch (static device globals; no allocation) -----------
__device__ float g_s[TOTAL];
__device__ float g_spart[NT_TILES * TOTAL];
__device__ float g_att[TOTAL];
__device__ int   g_start[NSEG + 1];
__device__ float g_poolp[PSPLIT * NSEG * D];   // split pooling partials
__device__ float g_W1t[D * DHEAD];
// fp16 operands, tile-contiguous + SW128 pre-swizzled
__device__ __align__(1024) unsigned char g_Fh[(size_t)TOTAL * D * 2];
__device__ __align__(1024) unsigned char g_Wh[(size_t)D * D * 2];

// ---------------------------- PTX helpers ----------------------------------
__device__ __forceinline__ uint32_t smem_u32(const void* p) {
    uint32_t a;
    asm("{ .reg .u64 t; cvta.to.shared.u64 t, %1; cvt.u32.u64 %0, t; }"
        : "=r"(a) : "l"(p));
    return a;
}
__device__ __forceinline__ uint32_t swz128(uint32_t b) {
    return b ^ ((b >> 3) & 0x70);
}

#define MBARRIER_INIT(addr, cnt) \
    asm volatile("mbarrier.init.shared.b64 [%0], %1;" :: "r"(addr), "r"(cnt) : "memory")
#define MBARRIER_EXPECT_TX(addr, bytes) \
    asm volatile("mbarrier.arrive.expect_tx.shared.b64 _, [%0], %1;" :: "r"(addr), "r"(bytes) : "memory")
#define MBARRIER_ARRIVE(addr) \
    asm volatile("mbarrier.arrive.release.cta.shared.b64 _, [%0];" :: "r"(addr) : "memory")
#define MBARRIER_WAIT_PARITY(addr, par) do {                                   \
    uint32_t _m = (addr); uint32_t _p = (par); uint32_t _d;                    \
    asm volatile("{\n\t.reg .pred p;\n\t"                                      \
        "mbarrier.try_wait.parity.acquire.cta.shared::cta.b64 p, [%1], %2;\n\t"\
        "selp.b32 %0, 1, 0, p;\n\t}" : "=r"(_d) : "r"(_m), "r"(_p) : "memory");\
    if (!_d) {                                                                 \
        asm volatile("{\n\t.reg .pred P1;\n\t"                                 \
        "WL_%=:\n\t"                                                           \
        "mbarrier.try_wait.parity.acquire.cta.shared::cta.b64 P1, [%0], %1, 0x989680;\n\t"\
        "@P1 bra.uni WD_%=;\n\t"                                               \
        "bra.uni WL_%=;\n\t"                                                   \
        "WD_%=:\n\t}" :: "r"(_m), "r"(_p) : "memory");                         \
    }                                                                          \
} while (0)

__device__ __forceinline__ void bulk_cp(uint32_t dst, const void* src,
                                        uint32_t bytes, uint32_t mbar) {
    asm volatile(
        "cp.async.bulk.shared::cluster.global.mbarrier::complete_tx::bytes [%0], [%1], %2, [%3];"
        :: "r"(dst), "l"(src), "r"(bytes), "r"(mbar) : "memory");
}

#define LDSM4(r, addr) \
    asm volatile("ldmatrix.sync.aligned.m8n8.x4.shared.b16 {%0,%1,%2,%3}, [%4];" \
        : "=r"((r)[0]), "=r"((r)[1]), "=r"((r)[2]), "=r"((r)[3]) : "r"(addr))

#define MMA16816(c, a, b0, b1) \
    asm volatile("mma.sync.aligned.m16n8k16.row.col.f32.f16.f16.f32 " \
        "{%0,%1,%2,%3}, {%4,%5,%6,%7}, {%8,%9}, {%0,%1,%2,%3};" \
        : "+f"((c)[0]), "+f"((c)[1]), "+f"((c)[2]), "+f"((c)[3]) \
        : "r"((a)[0]), "r"((a)[1]), "r"((a)[2]), "r"((a)[3]), "r"(b0), "r"(b1))

// ---------------------------------------------------------------------------
// fp32 -> fp16 pack helper
// ---------------------------------------------------------------------------
__device__ __forceinline__ uint4 pack8h(float4 x0, float4 x1) {
    uint32_t h[4];
    __half2 p0 = __floats2half2_rn(x0.x, x0.y); h[0] = *(uint32_t*)&p0;
    __half2 p1 = __floats2half2_rn(x0.z, x0.w); h[1] = *(uint32_t*)&p1;
    __half2 p2 = __floats2half2_rn(x1.x, x1.y); h[2] = *(uint32_t*)&p2;
    __half2 p3 = __floats2half2_rn(x1.z, x1.w); h[3] = *(uint32_t*)&p3;
    return make_uint4(h[0], h[1], h[2], h[3]);
}

// ---------------------------------------------------------------------------
// K0: merged prep kernel — convF + convW + misc in one launch.
// ---------------------------------------------------------------------------
__global__ void __launch_bounds__(512)
prep_kernel(const float* __restrict__ F, const float* __restrict__ W,
            const float* __restrict__ W1, const int* __restrict__ ids) {
    const int bid = blockIdx.x;
    if (bid < NB_CONVF) {
        int idx = bid * 512 + threadIdx.x;
        int row = idx / (D / 16), cg2 = idx - row * (D / 16);
        int mt = row >> 7, r = row & 127;
        int kc = cg2 >> 2, gi0 = (cg2 & 3) * 2;
        const float4* src = (const float4*)(F + (size_t)row * D + kc * 64 + gi0 * 8);
        uint4 h0 = pack8h(src[0], src[1]);
        uint4 h1 = pack8h(src[2], src[3]);
        size_t base = (size_t)(mt * KCHUNKS + kc) * ATILE_B;
        uint32_t rb = (uint32_t)(r * 128 + gi0 * 16);
        *(uint4*)(g_Fh + base + swz128(rb)) = h0;
        *(uint4*)(g_Fh + base + swz128(rb + 16)) = h1;
    } else if (bid < NB_CONVF + NB_CONVW) {
        int idx = (bid - NB_CONVF) * 512 + threadIdx.x;
        if (idx < D * (D / 8)) {
            int row = idx / (D / 8), cg = idx - row * (D / 8);
            int nt = row >> 7, r = row & 127;
            int kc = cg >> 3, gi = cg & 7;
            const float4* src = (const float4*)(W + (size_t)row * D + cg * 8);
            uint4 hi = pack8h(src[0], src[1]);
            size_t base = (size_t)(nt * KCHUNKS + kc) * BTILE_B;
            uint32_t off = swz128((uint32_t)(r * 128 + gi * 16));
            *(uint4*)(g_Wh + base + off) = hi;
        }
    } else {
        int idx = (bid - NB_CONVF - NB_CONVW) * 512 + threadIdx.x;
        if (idx < DHEAD * D) {
            int n = idx / D, k = idx - n * D;
            g_W1t[k * DHEAD + n] = W1[idx];
        }
        if (idx < TOTAL) {
            if (idx == 0) { g_start[ids[0]] = 0; g_start[NSEG] = TOTAL; }
            else if (ids[idx] != ids[idx - 1]) g_start[ids[idx]] = idx;
        }
    }
}

// ---------------------------------------------------------------------------
// K1: single-pass fp16 GEMM + tanh/dot-v epilogue, occupancy 2 (R10 exact).
// ---------------------------------------------------------------------------
__global__ void __launch_bounds__(256, 2)
gemm_tc_kernel(const float* __restrict__ bw, const float* __restrict__ v) {
    extern __shared__ __align__(16) char smem_raw[];
    __shared__ __align__(8) unsigned long long full_mb[NSTAGES];
    __shared__ __align__(8) unsigned long long empty_mb[NSTAGES];
    __shared__ float red[2][TILE_M];

    const uint32_t TILES = (smem_u32(smem_raw) + 1023) & ~1023u;
    const uint32_t FB = smem_u32(&full_mb[0]);
    const uint32_t EB = smem_u32(&empty_mb[0]);

    const int tid = threadIdx.x, wid = tid >> 5, lane = tid & 31;
    const int mt = blockIdx.x / NT_TILES, nt = blockIdx.x % NT_TILES;
    const int wm = wid >> 1, wn = wid & 1;   // 4 m-warps x 2 n-warps

    if (tid == 0) {
#pragma unroll
        for (int s = 0; s < NSTAGES; ++s) {
            MBARRIER_INIT(FB + s * 8, 1);
            MBARRIER_INIT(EB + s * 8, 256);
        }
    }
    __syncthreads();

    const unsigned char* aHi = g_Fh + (size_t)mt * KCHUNKS * ATILE_B;
    const unsigned char* bHi = g_Wh + (size_t)nt * KCHUNKS * BTILE_B;

    if (tid == 0) {
#pragma unroll
        for (int k = 0; k < NSTAGES - 1; ++k) {
            uint32_t st = TILES + k * STAGE_B;
            MBARRIER_EXPECT_TX(FB + k * 8, (uint32_t)STAGE_B);
            bulk_cp(st,           aHi + (size_t)k * ATILE_B, ATILE_B, FB + k * 8);
            bulk_cp(st + ATILE_B, bHi + (size_t)k * BTILE_B, BTILE_B, FB + k * 8);
        }
    }

    // ldmatrix address components (within tile, swizzled)
    const uint32_t xm = (lane & 7) << 4;
    const uint32_t a_rb = (uint32_t)(wm * 32 + (lane & 15)) * 128;
    const uint32_t a_cb = (uint32_t)((lane >> 4) * 16);
    const uint32_t b_rb = (uint32_t)(wn * 64 + (lane & 7) + ((lane >> 4) & 1) * 8) * 128;
    const uint32_t b_cb = (uint32_t)(((lane >> 3) & 1) * 16);

    float acc[2][8][4];
#pragma unroll
    for (int t = 0; t < 2; ++t)
#pragma unroll
        for (int j = 0; j < 8; ++j)
#pragma unroll
            for (int e = 0; e < 4; ++e) acc[t][j][e] = 0.f;

    for (int k = 0; k < KCHUNKS; ++k) {
        const int s = k % NSTAGES;
        MBARRIER_WAIT_PARITY(FB + s * 8, (uint32_t)((k / NSTAGES) & 1));

        if (tid == 0 && k + NSTAGES - 1 < KCHUNKS) {
            const int kn = k + NSTAGES - 1;
            const int s2 = kn % NSTAGES;
            if (kn >= NSTAGES)
                MBARRIER_WAIT_PARITY(EB + s2 * 8, (uint32_t)((kn / NSTAGES - 1) & 1));
            uint32_t st2 = TILES + s2 * STAGE_B;
            MBARRIER_EXPECT_TX(FB + s2 * 8, (uint32_t)STAGE_B);
            bulk_cp(st2,           aHi + (size_t)kn * ATILE_B, ATILE_B, FB + s2 * 8);
            bulk_cp(st2 + ATILE_B, bHi + (size_t)kn * BTILE_B, BTILE_B, FB + s2 * 8);
        }

        const uint32_t st = TILES + s * STAGE_B;
        const uint32_t stB = st + ATILE_B;
#pragma unroll
        for (int q = 0; q < 4; ++q) {
            uint32_t Ah[2][4], Bh[4][4];
            const uint32_t qa = (q * 32 + a_cb) ^ xm;
            const uint32_t qb = (q * 32 + b_cb) ^ xm;
#pragma unroll
            for (int t = 0; t < 2; ++t)
                LDSM4(Ah[t], st + a_rb + t * 2048 + qa);
#pragma unroll
            for (int g = 0; g < 4; ++g)
                LDSM4(Bh[g], stB + b_rb + g * 2048 + qb);
#pragma unroll
            for (int t = 0; t < 2; ++t)
#pragma unroll
                for (int g = 0; g < 4; ++g)
#pragma unroll
                    for (int h = 0; h < 2; ++h)
                        MMA16816(acc[t][g * 2 + h], Ah[t], Bh[g][h * 2], Bh[g][h * 2 + 1]);
        }
        MBARRIER_ARRIVE(EB + s * 8);
    }

    // epilogue: srow[r] = sum_n tanh(acc + bw[n]) * v[n]
#pragma unroll
    for (int t = 0; t < 2; ++t) {
        float s0 = 0.f, s1 = 0.f;
#pragma unroll
        for (int j = 0; j < 8; ++j) {
            int n0 = nt * TILE_N + wn * 64 + j * 8 + (lane & 3) * 2;
            float bw0 = __ldg(&bw[n0]),     v0 = __ldg(&v[n0]);
            float bw1 = __ldg(&bw[n0 + 1]), v1 = __ldg(&v[n0 + 1]);
            s0 += tanhf(acc[t][j][0] + bw0) * v0 + tanhf(acc[t][j][1] + bw1) * v1;
            s1 += tanhf(acc[t][j][2] + bw0) * v0 + tanhf(acc[t][j][3] + bw1) * v1;
        }
        s0 += __shfl_xor_sync(0xFFFFFFFFu, s0, 1);
        s0 += __shfl_xor_sync(0xFFFFFFFFu, s0, 2);
        s1 += __shfl_xor_sync(0xFFFFFFFFu, s1, 1);
        s1 += __shfl_xor_sync(0xFFFFFFFFu, s1, 2);
        if ((lane & 3) == 0) {
            int r = wm * 32 + t * 16 + (lane >> 2);
            red[wn][r] = s0;
            red[wn][r + 8] = s1;
        }
    }
    __syncthreads();
    if (tid < TILE_M)
        g_spart[nt * TOTAL + mt * TILE_M + tid] = red[0][tid] + red[1][tid];
}

// ---------------------------------------------------------------------------
// K2: per-segment stable softmax (folds the 10-way partial reduction inline)
// ---------------------------------------------------------------------------
__global__ void softmax_kernel() {
    __shared__ float sm[256];
    const int b = blockIdx.x, tid = threadIdx.x;
    const int s0 = g_start[b], s1 = g_start[b + 1];
    float m = -1e30f;
    for (int i = s0 + tid; i < s1; i += 256) {
        float t = 0.f;
#pragma unroll
        for (int nt = 0; nt < NT_TILES; ++nt) t += g_spart[nt * TOTAL + i];
        g_s[i] = t;
        m = fmaxf(m, t);
    }
    sm[tid] = m; __syncthreads();
    for (int st = 128; st >= 1; st >>= 1) {
        if (tid < st) sm[tid] = fmaxf(sm[tid], sm[tid + st]);
        __syncthreads();
    }
    m = sm[0]; __syncthreads();
    float z = 0.f;
    for (int i = s0 + tid; i < s1; i += 256) z += expf(g_s[i] - m);
    sm[tid] = z; __syncthreads();
    for (int st = 128; st >= 1; st >>= 1) {
        if (tid < st) sm[tid] += sm[tid + st];
        __syncthreads();
    }
    float inv = 1.f / sm[0];
    for (int i = s0 + tid; i < s1; i += 256)
        g_att[i] = expf(g_s[i] - m) * inv;
}

// ---------------------------------------------------------------------------
// K3: attention-weighted pooling, segment split 8-way for parallelism.
// grid (D/128, NSEG, PSPLIT); split z handles a deterministic eighth.
// ---------------------------------------------------------------------------
__global__ void pool_kernel(const float* __restrict__ F) {
    const int seg = blockIdx.y;
    const int z = blockIdx.z;
    const int col = blockIdx.x * 128 + threadIdx.x;
    const int s0 = g_start[seg], s1 = g_start[seg + 1];
    const int len = s1 - s0;
    const int i0 = s0 + (len * z) / PSPLIT;
    const int i1 = s0 + (len * (z + 1)) / PSPLIT;
    float acc = 0.f;
    int i = i0;
    for (; i + 3 < i1; i += 4) {
        float a0 = g_att[i], a1 = g_att[i + 1], a2 = g_att[i + 2], a3 = g_att[i + 3];
        float f0 = F[(size_t)(i + 0) * D + col];
        float f1 = F[(size_t)(i + 1) * D + col];
        float f2 = F[(size_t)(i + 2) * D + col];
        float f3 = F[(size_t)(i + 3) * D + col];
        acc = fmaf(a0, f0, acc); acc = fmaf(a1, f1, acc);
        acc = fmaf(a2, f2, acc); acc = fmaf(a3, f3, acc);
    }
    for (; i < i1; ++i) acc = fmaf(g_att[i], F[(size_t)i * D + col], acc);
    g_poolp[((size_t)z * NSEG + seg) * D + col] = acc;
}

// ---------------------------------------------------------------------------
// K4: MLP head (R15 style: one block per segment; sums PSPLIT partials)
// ---------------------------------------------------------------------------
__global__ void __launch_bounds__(DHEAD)
head_kernel(const float* __restrict__ b1, const float* __restrict__ W2,
            const float* __restrict__ b2, float* __restrict__ out) {
    __shared__ float p[D];
    __shared__ float red[DHEAD];
    const int seg = blockIdx.x, t = threadIdx.x;
    for (int k = t; k < D; k += DHEAD) {
        float s = 0.f;
#pragma unroll
        for (int z = 0; z < PSPLIT; ++z)
            s += g_poolp[((size_t)z * NSEG + seg) * D + k];
        p[k] = s;
    }
    __syncthreads();
    float acc = 0.f;
#pragma unroll 8
    for (int k = 0; k < D; ++k) acc = fmaf(p[k], g_W1t[k * DHEAD + t], acc);
    float h = fmaxf(acc + b1[t], 0.f);
    red[t] = h * W2[t];
    __syncthreads();
    for (int st = DHEAD / 2; st >= 1; st >>= 1) {
        if (t < st) red[t] += red[t + st];
        __syncthreads();
    }
    if (t == 0) out[seg] = red[0] + b2[0];
}

// ---------------------------------------------------------------------------
extern "C" void kernel_launch(void* const* d_in, const int* in_sizes, int n_in,
                              void* d_out, int out_size) {
    const float* features = (const float*)d_in[0];
    const float* Ww       = (const float*)d_in[1];
    const float* bw       = (const float*)d_in[2];
    const float* v        = (const float*)d_in[3];
    const float* W1       = (const float*)d_in[4];
    const float* b1       = (const float*)d_in[5];
    const float* W2       = (const float*)d_in[6];
    const float* b2       = (const float*)d_in[7];
    const int*   seg_ids  = (const int*)d_in[8];
    float* out = (float*)d_out;

    cudaFuncSetAttribute(gemm_tc_kernel,
                         cudaFuncAttributeMaxDynamicSharedMemorySize, DSMEM);

    prep_kernel<<<NB_PREP, 512>>>(features, Ww, W1, seg_ids);
    gemm_tc_kernel<<<MT_TILES * NT_TILES, 256, DSMEM>>>(bw, v);
    softmax_kernel<<<NSEG, 256>>>();
    pool_kernel<<<dim3(D / 128, NSEG, PSPLIT), 128>>>(features);
    head_kernel<<<NSEG, DHEAD>>>(b1, W2, b2, out);
}